// round 16
// baseline (speedup 1.0000x reference)
#include <cuda_runtime.h>
#include <cuda_fp16.h>
#include <math.h>
#include <stdint.h>

#define NN   40960
#define SS   4096
#define EE   81920
#define DD   64
#define HH   100
#define FIN  321
#define VV   50000

// ---------------- scratch (device globals; no allocation allowed) ----------------
__device__ float    g_x[NN * FIN];
__device__ float    g_xl[SS * FIN];
__device__ float    g_h[NN * HH];
__device__ float    g_msg[NN * HH];
__device__ float    g_gi[NN * 3 * HH];
__device__ float    g_gh[NN * 3 * HH];
__device__ int      g_deg[NN];
__device__ float    g_dinv[NN];
__device__ int      g_lastidx[SS];
__device__ float    g_last[SS * HH];
__device__ float    g_g1[NN * HH];
__device__ float    g_gate[NN];
__device__ float    g_w[NN];
__device__ unsigned g_gmax[SS];
__device__ float    g_wsum[SS];
__device__ float    g_pooled[SS * HH];

// ---------------- f32x2 packed-math helpers (Blackwell FFMA2) ----------------
__device__ __forceinline__ unsigned long long f2_pack(float lo, float hi) {
    unsigned long long r;
    asm("mov.b64 %0, {%1, %2};" : "=l"(r) : "f"(lo), "f"(hi));
    return r;
}
__device__ __forceinline__ float2 f2_unpack(unsigned long long v) {
    float lo, hi;
    asm("mov.b64 {%0, %1}, %2;" : "=f"(lo), "=f"(hi) : "l"(v));
    return make_float2(lo, hi);
}
__device__ __forceinline__ unsigned long long f2_fma(unsigned long long a,
                                                     unsigned long long b,
                                                     unsigned long long c) {
    asm("fma.rn.f32x2 %0, %1, %2, %3;" : "=l"(c) : "l"(a), "l"(b), "l"(c));
    return c;
}

// ---------------- fp16 mma.sync (plain HMMA path) ----------------
__device__ __forceinline__ void mma_16n8k16_f16(float* d,
                                                const uint32_t* a, const uint32_t* b) {
    asm volatile(
        "mma.sync.aligned.m16n8k16.row.col.f32.f16.f16.f32 "
        "{%0, %1, %2, %3}, {%4, %5, %6, %7}, {%8, %9}, {%0, %1, %2, %3};"
        : "+f"(d[0]), "+f"(d[1]), "+f"(d[2]), "+f"(d[3])
        : "r"(a[0]), "r"(a[1]), "r"(a[2]), "r"(a[3]), "r"(b[0]), "r"(b[1]));
}

// ---------------- helpers ----------------
__device__ __forceinline__ unsigned enc_f(float f) {
    unsigned u = __float_as_uint(f);
    return (u & 0x80000000u) ? ~u : (u | 0x80000000u);
}
__device__ __forceinline__ float dec_f(unsigned e) {
    return (e & 0x80000000u) ? __uint_as_float(e ^ 0x80000000u) : __uint_as_float(~e);
}
__device__ __forceinline__ float fast_sigmoid(float x) {
    return 1.f / (1.f + __expf(-x));
}
__device__ __forceinline__ float fast_tanh(float x) {
    float t = __expf(-2.f * fabsf(x));
    float y = (1.f - t) / (1.f + t);
    return copysignf(y, x);
}

// ---------------- init / zero ----------------
__global__ void k_init_small() {
    int i = blockIdx.x * blockDim.x + threadIdx.x;
    if (i < NN) g_deg[i] = 0;
    if (i < SS) { g_lastidx[i] = -1; g_gmax[i] = 0u; g_wsum[i] = 0.f; }
}
__global__ void k_zero_big() {
    int i = blockIdx.x * blockDim.x + threadIdx.x;
    if (i < NN * HH) g_msg[i] = 0.f;
    if (i < SS * HH) g_pooled[i] = 0.f;
}

// ---------------- node feature gather: x[n, 0..320] ----------------
__global__ void k_gather_x(const float* __restrict__ price,
                           const int* __restrict__ cat, const int* __restrict__ sub,
                           const int* __restrict__ elem, const int* __restrict__ brand,
                           const int* __restrict__ pid,
                           const float* __restrict__ ecat, const float* __restrict__ esub,
                           const float* __restrict__ eelem, const float* __restrict__ ebrand,
                           const float* __restrict__ eitem) {
    int n = blockIdx.x;
    int j = threadIdx.x;
    if (j >= FIN) return;
    float v;
    if (j == 0) {
        v = price[n];
    } else {
        int s = (j - 1) >> 6;
        int o = (j - 1) & 63;
        const float* tab;
        int idx;
        switch (s) {
            case 0:  tab = ecat;   idx = cat[n];   break;
            case 1:  tab = esub;   idx = sub[n];   break;
            case 2:  tab = eelem;  idx = elem[n];  break;
            case 3:  tab = ebrand; idx = brand[n]; break;
            default: tab = eitem;  idx = pid[n];   break;
        }
        v = tab[idx * DD + o];
    }
    g_x[n * FIN + j] = v;
}

// ---------------- tiled SGEMM v3: k-pair SIMD, C = A @ B + bias, optional relu ----------------
// f32x2 lanes span k-parity: acc ull holds (sum over even k, sum over odd k) per (m,n);
// horizontal sum at the end. A loads are natural LDS.64 pairs (no packs in inner loop);
// B stored k-pair-interleaved as ull. 64x64 block tile, 4x4 ull accs per thread.
// Per k2-step: 4 LDS.64 + 2 LDS.128 + 16 FFMA2 = 22 issues / 32 MACs.
__global__ void k_sgemm(const float* __restrict__ A, const float* __restrict__ B,
                        const float* __restrict__ bias, float* __restrict__ C,
                        int M, int Nn, int K, int relu) {
    __shared__ unsigned long long As2[64][9];   // [row][k2], (A[m][2k2], A[m][2k2+1])
    __shared__ unsigned long long Bs2[8][64];   // [k2][n],  (B[2k2][n], B[2k2+1][n])
    int tid = threadIdx.x;
    int tx = tid & 15, ty = tid >> 4;           // tx: 4 cols, ty: 4 rows
    int m0 = blockIdx.y * 64, n0 = blockIdx.x * 64;

    unsigned long long acc2[4][4];
#pragma unroll
    for (int i = 0; i < 4; i++)
#pragma unroll
        for (int j = 0; j < 4; j++) acc2[i][j] = 0ull;

    for (int k0 = 0; k0 < K; k0 += 16) {
        // A tile: 64 rows x 8 k2 = 512 pairs, 2/thread
        for (int i = tid; i < 64 * 8; i += 256) {
            int mi = i >> 3, k2 = i & 7;
            int m = m0 + mi, k = k0 + 2 * k2;
            float a0 = (m < M && k < K)     ? A[m * K + k]     : 0.f;
            float a1 = (m < M && k + 1 < K) ? A[m * K + k + 1] : 0.f;
            As2[mi][k2] = f2_pack(a0, a1);
        }
        // B tile: 8 k2 x 64 n = 512 pairs, 2/thread (coalesced over n per row)
        for (int i = tid; i < 8 * 64; i += 256) {
            int k2 = i >> 6, n = i & 63;
            int k = k0 + 2 * k2, gn = n0 + n;
            float b0 = (k < K && gn < Nn)     ? B[k * Nn + gn]       : 0.f;
            float b1 = (k + 1 < K && gn < Nn) ? B[(k + 1) * Nn + gn] : 0.f;
            Bs2[k2][n] = f2_pack(b0, b1);
        }
        __syncthreads();
#pragma unroll
        for (int k2 = 0; k2 < 8; k2++) {
            ulonglong2 b01 = *(const ulonglong2*)&Bs2[k2][tx * 4];
            ulonglong2 b23 = *(const ulonglong2*)&Bs2[k2][tx * 4 + 2];
#pragma unroll
            for (int i = 0; i < 4; i++) {
                unsigned long long ap = As2[ty * 4 + i][k2];
                acc2[i][0] = f2_fma(ap, b01.x, acc2[i][0]);
                acc2[i][1] = f2_fma(ap, b01.y, acc2[i][1]);
                acc2[i][2] = f2_fma(ap, b23.x, acc2[i][2]);
                acc2[i][3] = f2_fma(ap, b23.y, acc2[i][3]);
            }
        }
        __syncthreads();
    }

#pragma unroll
    for (int i = 0; i < 4; i++) {
        int m = m0 + ty * 4 + i;
        if (m >= M) continue;
#pragma unroll
        for (int j = 0; j < 4; j++) {
            int n = n0 + tx * 4 + j;
            if (n >= Nn) continue;
            float2 p = f2_unpack(acc2[i][j]);
            float v = p.x + p.y + bias[n];
            if (relu) v = fmaxf(v, 0.f);
            C[m * Nn + n] = v;
        }
    }
}

// ---------------- degree + inverse ----------------
__global__ void k_deg(const int* __restrict__ eidx) {
    int e = blockIdx.x * blockDim.x + threadIdx.x;
    if (e < EE) atomicAdd(&g_deg[eidx[EE + e]], 1);
}
__global__ void k_dinv() {
    int n = blockIdx.x * blockDim.x + threadIdx.x;
    if (n < NN) g_dinv[n] = (g_deg[n] > 0) ? (1.f / (float)g_deg[n]) : 0.f;
}

// ---------------- edge scatter: msg[dst] += h[src] * dinv[dst]  (mean fused) ----------------
__global__ void k_scatter(const int* __restrict__ eidx) {
    int e = blockIdx.x;
    int d = threadIdx.x;
    if (d >= HH) return;
    int s = eidx[e];
    int t = eidx[EE + e];
    atomicAdd(&g_msg[t * HH + d], g_h[s * HH + d] * g_dinv[t]);
}

// ---------------- GRU cell elementwise, fused with last-node add ----------------
__global__ void k_gru(const int* __restrict__ batch) {
    int i = blockIdx.x * blockDim.x + threadIdx.x;
    if (i >= NN * HH) return;
    int n = i / HH, j = i % HH;
    const float* gi = g_gi + n * 3 * HH;
    const float* gh = g_gh + n * 3 * HH;
    float r  = fast_sigmoid(gi[j] + gh[j]);
    float z  = fast_sigmoid(gi[HH + j] + gh[HH + j]);
    float nn = fast_tanh(gi[2 * HH + j] + r * gh[2 * HH + j]);
    float h  = g_h[i];
    g_h[i] = (1.f - z) * nn + z * h + g_last[batch[n] * HH + j];
}

// ---------------- last index per session + gather ----------------
__global__ void k_lastidx(const int* __restrict__ batch) {
    int n = blockIdx.x * blockDim.x + threadIdx.x;
    if (n < NN) atomicMax(&g_lastidx[batch[n]], n);
}
__global__ void k_gather_xl() {
    int s = blockIdx.x;
    int j = threadIdx.x;
    if (j >= FIN) return;
    g_xl[s * FIN + j] = g_x[g_lastidx[s] * FIN + j];
}

// ---------------- attention gate ----------------
__global__ void k_gate(const float* __restrict__ wg2, const float* __restrict__ bg2,
                       const int* __restrict__ batch) {
    int w = (blockIdx.x * blockDim.x + threadIdx.x) >> 5;
    int lane = threadIdx.x & 31;
    if (w >= NN) return;
    const float* row = g_g1 + w * HH;
    float s = 0.f;
    for (int k = lane; k < HH; k += 32) s += row[k] * wg2[k];
#pragma unroll
    for (int o = 16; o; o >>= 1) s += __shfl_xor_sync(0xffffffffu, s, o);
    if (lane == 0) {
        float g = s + bg2[0];
        g_gate[w] = g;
        atomicMax(&g_gmax[batch[w]], enc_f(g));
    }
}
__global__ void k_softw(const int* __restrict__ batch) {
    int n = blockIdx.x * blockDim.x + threadIdx.x;
    if (n >= NN) return;
    int b = batch[n];
    float wv = __expf(g_gate[n] - dec_f(g_gmax[b]));
    g_w[n] = wv;
    atomicAdd(&g_wsum[b], wv);
}
__global__ void k_pool(const int* __restrict__ batch) {
    int n = blockIdx.x;
    int d = threadIdx.x;
    if (d >= HH) return;
    int b = batch[n];
    float alpha = g_w[n] / g_wsum[b];
    atomicAdd(&g_pooled[b * HH + d], alpha * g_h[n * HH + d]);
}

// ================= FC via fp16 mma.sync m16n8k16 (native HMMA path) =================
// out[4096,50000] = pooled @ W_fc + b_fc  (fp16 inputs, fp32 accumulate)
#define FKH 120
#define FC_SMEM_H (128 * FKH * 2 * 2 + 512)   /* 61952 bytes */
#define FC_MT 8                                /* M-tiles per CTA (grid.y = 4) */

__global__ void __launch_bounds__(256, 2)
k_fc(const float* __restrict__ pooled, const float* __restrict__ W,
     const float* __restrict__ bias, float* __restrict__ C) {
    extern __shared__ __align__(16) char smraw[];
    __half*   BsH  = (__half*)smraw;                       // [128][FKH]
    uint32_t* Bs32 = (uint32_t*)smraw;                     // word view, stride 60
    uint32_t* As32 = (uint32_t*)(smraw + 128 * FKH * 2);   // word view, stride 60
    float*    biasS = (float*)(smraw + 2 * 128 * FKH * 2); // [128]
    int tid = threadIdx.x;
    int lane = tid & 31, wid = tid >> 5;
    int n0 = blockIdx.x * 128;
    int m_begin = blockIdx.y * FC_MT;

    for (int i = tid; i < 2 * 128 * (FKH / 2); i += 256) ((uint32_t*)smraw)[i] = 0u;
    if (tid < 128) biasS[tid] = (n0 + tid < VV) ? bias[n0 + tid] : 0.f;
    __syncthreads();

    for (int i = tid; i < HH * 128; i += 256) {
        int k = i >> 7, n = i & 127;
        int gn = n0 + n;
        if (gn < VV) BsH[n * FKH + k] = __float2half_rn(W[(size_t)k * VV + gn]);
    }

    int wm = wid >> 2, wn = wid & 3;
    int g = lane >> 2, tg = lane & 3;

    for (int it = 0; it < FC_MT; it++) {
        int m0 = (m_begin + it) * 128;
        for (int p = tid; p < 128 * (HH / 2); p += 256) {
            int r = p / (HH / 2), kp = p - r * (HH / 2);
            float2 v = *(const float2*)&pooled[(m0 + r) * HH + 2 * kp];
            __half2 h2 = __floats2half2_rn(v.x, v.y);
            As32[r * (FKH / 2) + kp] = *(uint32_t*)&h2;
        }
        __syncthreads();

        float acc[4][4][4];
#pragma unroll
        for (int mi = 0; mi < 4; mi++)
#pragma unroll
            for (int ni = 0; ni < 4; ni++)
#pragma unroll
                for (int j = 0; j < 4; j++) acc[mi][ni][j] = 0.f;

#pragma unroll
        for (int ks = 0; ks < 7; ks++) {
            int kw = ks * 8;
            uint32_t af[4][4], bf[4][2];
#pragma unroll
            for (int mi = 0; mi < 4; mi++) {
                int r0 = wm * 64 + mi * 16 + g;
                const uint32_t* ap = &As32[r0 * 60 + kw + tg];
                af[mi][0] = ap[0];
                af[mi][1] = ap[8 * 60];
                af[mi][2] = ap[4];
                af[mi][3] = ap[8 * 60 + 4];
            }
#pragma unroll
            for (int ni = 0; ni < 4; ni++) {
                int nb = wn * 32 + ni * 8 + g;
                const uint32_t* bp = &Bs32[nb * 60 + kw + tg];
                bf[ni][0] = bp[0];
                bf[ni][1] = bp[4];
            }
#pragma unroll
            for (int mi = 0; mi < 4; mi++)
#pragma unroll
                for (int ni = 0; ni < 4; ni++)
                    mma_16n8k16_f16(acc[mi][ni], af[mi], bf[ni]);
        }

#pragma unroll
        for (int mi = 0; mi < 4; mi++) {
            int r = m0 + wm * 64 + mi * 16 + g;
            size_t rb0 = (size_t)r * VV;
            size_t rb1 = (size_t)(r + 8) * VV;
#pragma unroll
            for (int ni = 0; ni < 4; ni++) {
                int cn = wn * 32 + ni * 8 + 2 * tg;
                int gn = n0 + cn;
                if (gn < VV) {
                    float bx = biasS[cn], by = biasS[cn + 1];
                    *(float2*)&C[rb0 + gn] = make_float2(acc[mi][ni][0] + bx,
                                                         acc[mi][ni][1] + by);
                    *(float2*)&C[rb1 + gn] = make_float2(acc[mi][ni][2] + bx,
                                                         acc[mi][ni][3] + by);
                }
            }
        }
        __syncthreads();
    }
}

// ---------------- launch ----------------
extern "C" void kernel_launch(void* const* d_in, const int* in_sizes, int n_in,
                              void* d_out, int out_size) {
    const float* price    = (const float*)d_in[0];
    const int*   category = (const int*)d_in[1];
    const int*   sub      = (const int*)d_in[2];
    const int*   elem     = (const int*)d_in[3];
    const int*   brand    = (const int*)d_in[4];
    const int*   pid      = (const int*)d_in[5];
    const int*   eidx     = (const int*)d_in[6];
    const int*   batch    = (const int*)d_in[7];
    const float* ecat     = (const float*)d_in[8];
    const float* esub     = (const float*)d_in[9];
    const float* eelem    = (const float*)d_in[10];
    const float* ebrand   = (const float*)d_in[11];
    const float* eitem    = (const float*)d_in[12];
    const float* W_msg    = (const float*)d_in[13];
    const float* b_msg    = (const float*)d_in[14];
    const float* W_ih     = (const float*)d_in[15];
    const float* W_hh     = (const float*)d_in[16];
    const float* b_ih     = (const float*)d_in[17];
    const float* b_hh     = (const float*)d_in[18];
    const float* W_last   = (const float*)d_in[19];
    const float* b_last   = (const float*)d_in[20];
    const float* W_g1     = (const float*)d_in[21];
    const float* b_g1     = (const float*)d_in[22];
    const float* W_g2     = (const float*)d_in[23];
    const float* b_g2     = (const float*)d_in[24];
    const float* W_fc     = (const float*)d_in[25];
    const float* b_fc     = (const float*)d_in[26];
    float* out = (float*)d_out;

    float *p_x, *p_xl, *p_h, *p_msg, *p_gi, *p_gh, *p_last, *p_g1, *p_pooled;
    cudaGetSymbolAddress((void**)&p_x,      g_x);
    cudaGetSymbolAddress((void**)&p_xl,     g_xl);
    cudaGetSymbolAddress((void**)&p_h,      g_h);
    cudaGetSymbolAddress((void**)&p_msg,    g_msg);
    cudaGetSymbolAddress((void**)&p_gi,     g_gi);
    cudaGetSymbolAddress((void**)&p_gh,     g_gh);
    cudaGetSymbolAddress((void**)&p_last,   g_last);
    cudaGetSymbolAddress((void**)&p_g1,     g_g1);
    cudaGetSymbolAddress((void**)&p_pooled, g_pooled);

    cudaFuncSetAttribute(k_fc, cudaFuncAttributeMaxDynamicSharedMemorySize, FC_SMEM_H);

    // init scratch
    k_init_small<<<(NN + 255) / 256, 256>>>();
    k_zero_big<<<(NN * HH + 255) / 256, 256>>>();

    // node features
    k_gather_x<<<NN, 352>>>(price, category, sub, elem, brand, pid,
                            ecat, esub, eelem, ebrand, eitem);

    // h0 = x @ W_msg + b_msg
    {
        dim3 g((HH + 63) / 64, (NN + 63) / 64);
        k_sgemm<<<g, 256>>>(p_x, W_msg, b_msg, p_h, NN, HH, FIN, 0);
    }

    // last-node features (independent of GRU chain; needed by fused k_gru)
    k_lastidx<<<(NN + 255) / 256, 256>>>(batch);
    k_gather_xl<<<SS, 352>>>();
    {
        dim3 g((HH + 63) / 64, (SS + 63) / 64);
        k_sgemm<<<g, 256>>>(p_xl, W_last, b_last, p_last, SS, HH, FIN, 0);
    }

    // degrees
    k_deg<<<(EE + 255) / 256, 256>>>(eidx);
    k_dinv<<<(NN + 255) / 256, 256>>>();

    // mean aggregation (dinv fused into scatter)
    k_scatter<<<EE, 128>>>(eidx);

    // GRU gates
    {
        dim3 g((3 * HH + 63) / 64, (NN + 63) / 64);
        k_sgemm<<<g, 256>>>(p_msg, W_ih, b_ih, p_gi, NN, 3 * HH, HH, 0);
        k_sgemm<<<g, 256>>>(p_h,   W_hh, b_hh, p_gh, NN, 3 * HH, HH, 0);
    }
    // GRU + last-node add fused
    k_gru<<<(NN * HH + 255) / 256, 256>>>(batch);

    // attention gate MLP
    {
        dim3 g((HH + 63) / 64, (NN + 63) / 64);
        k_sgemm<<<g, 256>>>(p_h, W_g1, b_g1, p_g1, NN, HH, HH, 1);
    }
    k_gate<<<(NN * 32 + 255) / 256, 256>>>(W_g2, b_g2, batch);
    k_softw<<<(NN + 255) / 256, 256>>>(batch);
    k_pool<<<NN, 128>>>(batch);

    // final scoring: fp16 mma.sync m16n8k16, 2 CTAs/SM
    {
        dim3 g((VV + 127) / 128, 4);
        k_fc<<<g, 256, FC_SMEM_H>>>(p_pooled, W_fc, b_fc, out);
    }
}